// round 11
// baseline (speedup 1.0000x reference)
#include <cuda_runtime.h>

// Scratch (no device allocation allowed).
// Transposed layout: g_part[entry][block]; blocks 8b..8b+7 belong to batch b,
// so each batch's 8 partials of one entry are two aligned float4s.
__device__ __align__(16) float g_part[36][32];
__device__ unsigned int g_count = 0;

// Weight of packed upper-triangular entry e=(i,j), i<=j, of the 8x8 moment
// matrix M in loss_b = sum_e w_e * M_b[e]^2:
//   both in P-block (0..3): diag 1, off-diag 2   (||PP^T||_F^2)
//   i in P, j in S (4..7):  -2                   (-2||PS^T||_F^2)
//   both in S-block:        diag 1, off-diag 2   (||SS^T||_F^2)
__constant__ float c_w[36] = {
    1.f, 2.f, 2.f, 2.f, -2.f, -2.f, -2.f, -2.f,   // i=0
    1.f, 2.f, 2.f, -2.f, -2.f, -2.f, -2.f,        // i=1
    1.f, 2.f, -2.f, -2.f, -2.f, -2.f,             // i=2
    1.f, -2.f, -2.f, -2.f, -2.f,                  // i=3
    1.f, 2.f, 2.f, 2.f,                           // i=4
    1.f, 2.f, 2.f,                                // i=5
    1.f, 2.f,                                     // i=6
    1.f                                           // i=7
};

// Release-arrive: single acq_rel atomic orders this block's prior stores
// before the increment; the last arrival's acquire side makes every other
// block's released stores visible. Replaces two __threadfence() MEMBARs.
__device__ __forceinline__ unsigned int arrive_acq_rel(unsigned int* ctr)
{
    unsigned int old;
    asm volatile("atom.global.add.acq_rel.gpu.u32 %0, [%1], 1;"
                 : "=r"(old) : "l"(ctr) : "memory");
    return old;
}

// grid = 32 blocks (8 slices per batch), 128 threads (1 warp per SMSP).
// Each thread owns one float4 group (4 spatial positions).
// v_n = [p_n/||p_n||, s_n/||s_n||] in R^8; block accumulates the 36 unique
// entries of sum_n v_n v_n^T for its slice. Last arriving block's warp 0
// reduces per-BATCH and evaluates
//   loss = sum_b (||PP^T||^2 - 2||PS^T||^2 + ||SS^T||^2) / (B*N*N)
// via the exact identity sum_nm (a_n.a_m)(b_n.b_m) = ||A B^T||_F^2.
__global__ void __launch_bounds__(128, 1)
cosine_ssm_fused_kernel(const float* __restrict__ xp,
                        const float* __restrict__ xs,
                        float* __restrict__ out)
{
    constexpr int N = 4096;
    const int blk   = blockIdx.x;
    const int b     = blk >> 3;       // batch (8 blocks per batch)
    const int slice = blk & 7;        // eighth of the spatial dim
    const int t     = threadIdx.x;
    const int warp  = t >> 5;
    const int lane  = t & 31;

    const float* pb = xp + b * 4 * N;
    const float* sb = xs + b * 4 * N;
    const int g = (slice * 512) + t * 4;   // starting spatial index

    float pv[4][4], sv[4][4];
#pragma unroll
    for (int c = 0; c < 4; ++c) {
        float4 a = *reinterpret_cast<const float4*>(pb + c * N + g);
        pv[c][0] = a.x; pv[c][1] = a.y; pv[c][2] = a.z; pv[c][3] = a.w;
        float4 q = *reinterpret_cast<const float4*>(sb + c * N + g);
        sv[c][0] = q.x; sv[c][1] = q.y; sv[c][2] = q.z; sv[c][3] = q.w;
    }

    float acc[36];
#pragma unroll
    for (int i = 0; i < 36; ++i) acc[i] = 0.0f;

#pragma unroll
    for (int k = 0; k < 4; ++k) {
        float sumsq_p = pv[0][k] * pv[0][k] + pv[1][k] * pv[1][k]
                      + pv[2][k] * pv[2][k] + pv[3][k] * pv[3][k];
        float sumsq_s = sv[0][k] * sv[0][k] + sv[1][k] * sv[1][k]
                      + sv[2][k] * sv[2][k] + sv[3][k] * sv[3][k];
        // x / max(||x||, 1e-12)  ==  x * rsqrt(max(||x||^2, 1e-24))
        float ip = rsqrtf(fmaxf(sumsq_p, 1e-24f));
        float is = rsqrtf(fmaxf(sumsq_s, 1e-24f));
        float v[8];
#pragma unroll
        for (int c = 0; c < 4; ++c) {
            v[c]     = pv[c][k] * ip;
            v[4 + c] = sv[c][k] * is;
        }
        int idx = 0;
#pragma unroll
        for (int i = 0; i < 8; ++i)
#pragma unroll
            for (int jj = i; jj < 8; ++jj)
                acc[idx++] += v[i] * v[jj];
    }

    // Partial warp reduce: 2 butterfly rounds (72 SHFL).
    // Lanes 0..7 hold sums over lanes {l, l+8, l+16, l+24}.
#pragma unroll
    for (int off = 16; off >= 8; off >>= 1)
#pragma unroll
        for (int i = 0; i < 36; ++i)
            acc[i] += __shfl_down_sync(0xffffffffu, acc[i], off);

    // Padded smem: stride 37 (== 5 mod 32) -> conflict-free column reads.
    __shared__ float red[32][37];
    if (lane < 8) {
        float* row = red[warp * 8 + lane];
#pragma unroll
        for (int i = 0; i < 36; ++i) row[i] = acc[i];
    }
    __syncthreads();

    // Warps 2,3 are done after publishing their smem rows.
    if (warp >= 2) return;

    // Block reduce spread over warps 0 and 1: thread t (t<36) sums column t.
    // Pairwise tree (depth 5) instead of a serial 32-deep FADD chain.
    if (t < 36) {
        float v[32];
#pragma unroll
        for (int r = 0; r < 32; ++r) v[r] = red[r][t];   // 32 independent LDS
#pragma unroll
        for (int stride = 16; stride > 0; stride >>= 1)
#pragma unroll
            for (int r = 0; r < stride; ++r)
                v[r] += v[r + stride];
        g_part[t][blk] = v[0];
    }
    // Named barrier over warps 0+1 only (warps 2,3 have exited).
    asm volatile("bar.sync 1, 64;" ::: "memory");

    if (warp != 0) return;

    unsigned int old = 0;
    if (lane == 0)
        old = arrive_acq_rel(&g_count);   // release block's stores + arrive
    old = __shfl_sync(0xffffffffu, old, 0);
    if (old != 31u) return;

    // ---- last block, warp 0: per-BATCH reduce + weighted square ----
    // (acquire side of the acq_rel atomic makes all releases visible)

    // lane l handles entry l; lanes 0..3 also handle entries 32..35.
    // Each batch's 8 block-partials of one entry = two float4s.
    float val = 0.0f;
    {
        const float4* r = reinterpret_cast<const float4*>(g_part[lane]);
        float ss[4];
#pragma unroll
        for (int bb = 0; bb < 4; ++bb) {
            float4 q0 = __ldcg(r + bb * 2);
            float4 q1 = __ldcg(r + bb * 2 + 1);
            float m = ((q0.x + q0.y) + (q0.z + q0.w))
                    + ((q1.x + q1.y) + (q1.z + q1.w));
            ss[bb] = m * m;
        }
        val = c_w[lane] * ((ss[0] + ss[1]) + (ss[2] + ss[3]));
    }
    if (lane < 4) {
        const float4* r = reinterpret_cast<const float4*>(g_part[32 + lane]);
        float ss[4];
#pragma unroll
        for (int bb = 0; bb < 4; ++bb) {
            float4 q0 = __ldcg(r + bb * 2);
            float4 q1 = __ldcg(r + bb * 2 + 1);
            float m = ((q0.x + q0.y) + (q0.z + q0.w))
                    + ((q1.x + q1.y) + (q1.z + q1.w));
            ss[bb] = m * m;
        }
        val += c_w[32 + lane] * ((ss[0] + ss[1]) + (ss[2] + ss[3]));
    }

#pragma unroll
    for (int off = 16; off > 0; off >>= 1)
        val += __shfl_down_sync(0xffffffffu, val, off);

    if (lane == 0) {
        out[0] = val * (1.0f / (4.0f * 4096.0f * 4096.0f));
        g_count = 0;   // reset for the next graph replay
    }
}

extern "C" void kernel_launch(void* const* d_in, const int* in_sizes, int n_in,
                              void* d_out, int out_size)
{
    const float* xp = (const float*)d_in[0];  // x_pred [4,4,64,64] fp32
    const float* xs = (const float*)d_in[1];  // x_src  [4,4,64,64] fp32
    cosine_ssm_fused_kernel<<<32, 128>>>(xp, xs, (float*)d_out);
}

// round 12
// speedup vs baseline: 1.0294x; 1.0294x over previous
#include <cuda_runtime.h>
#include <cstdint>

// Weight of packed upper-triangular entry e=(i,j), i<=j, of the 8x8 moment
// matrix M in loss_b = sum_e w_e * M_b[e]^2:
//   both in P-block (0..3): diag 1, off-diag 2   (||PP^T||_F^2)
//   i in P, j in S (4..7):  -2                   (-2||PS^T||_F^2)
//   both in S-block:        diag 1, off-diag 2   (||SS^T||_F^2)
__constant__ float c_w[36] = {
    1.f, 2.f, 2.f, 2.f, -2.f, -2.f, -2.f, -2.f,   // i=0
    1.f, 2.f, 2.f, -2.f, -2.f, -2.f, -2.f,        // i=1
    1.f, 2.f, -2.f, -2.f, -2.f, -2.f,             // i=2
    1.f, -2.f, -2.f, -2.f, -2.f,                  // i=3
    1.f, 2.f, 2.f, 2.f,                           // i=4
    1.f, 2.f, 2.f,                                // i=5
    1.f, 2.f,                                     // i=6
    1.f                                           // i=7
};

__device__ __forceinline__ uint32_t smem_u32(const void* p)
{
    uint32_t a;
    asm("{ .reg .u64 t; cvta.to.shared.u64 t, %1; cvt.u32.u64 %0, t; }"
        : "=r"(a) : "l"(p));
    return a;
}

// Map a local smem address to the same offset in cluster rank 0's smem.
__device__ __forceinline__ uint32_t mapa_rank0(uint32_t local_addr)
{
    uint32_t r;
    asm("mapa.shared::cluster.u32 %0, %1, 0;" : "=r"(r) : "r"(local_addr));
    return r;
}

// One cluster of 8 CTAs x 512 threads. CTA blk: batch b = blk>>1,
// half = blk&1 of the 4096 spatial positions. Each thread owns one float4
// group (4 positions). v_n = [p_n/||p_n||, s_n/||s_n||] in R^8; each CTA
// accumulates the 36 unique entries of sum_n v_n v_n^T for its slice and
// writes them into rank 0's smem via DSMEM, then arrives on rank 0's
// mbarrier. Rank 0 waits (8 arrivals) and evaluates
//   loss = sum_b (||PP^T||^2 - 2||PS^T||^2 + ||SS^T||^2) / (B*N*N)
// via the exact identity sum_nm (a_n.a_m)(b_n.b_m) = ||A B^T||_F^2.
// No global scratch, no atomics, no cross-replay device state.
__global__ void __launch_bounds__(512, 1) __cluster_dims__(8, 1, 1)
cosine_ssm_cluster_kernel(const float* __restrict__ xp,
                          const float* __restrict__ xs,
                          float* __restrict__ out)
{
    constexpr int N = 4096;
    __shared__ float red[64][37];   // stride 37 -> conflict-free columns
    __shared__ float part[36][9];   // [entry][rank], 9-pad -> conflict-free
    __shared__ __align__(8) unsigned long long mbar;

    const int blk  = blockIdx.x;
    const int b    = blk >> 1;      // batch (2 CTAs per batch)
    const int half = blk & 1;       // half of the spatial dim
    const int t    = threadIdx.x;
    const int warp = t >> 5;
    const int lane = t & 31;

    const uint32_t mbar_addr = smem_u32(&mbar);
    if (t == 0)
        asm volatile("mbarrier.init.shared.b64 [%0], 8;"
                     :: "r"(mbar_addr) : "memory");

    // Issue all global loads FIRST so the cluster.sync below overlaps the
    // DRAM miss latency.
    const float* pb = xp + b * 4 * N;
    const float* sb = xs + b * 4 * N;
    const int g = half * 2048 + t * 4;   // starting spatial index

    float pv[4][4], sv[4][4];
#pragma unroll
    for (int c = 0; c < 4; ++c) {
        float4 a = *reinterpret_cast<const float4*>(pb + c * N + g);
        pv[c][0] = a.x; pv[c][1] = a.y; pv[c][2] = a.z; pv[c][3] = a.w;
        float4 q = *reinterpret_cast<const float4*>(sb + c * N + g);
        sv[c][0] = q.x; sv[c][1] = q.y; sv[c][2] = q.z; sv[c][3] = q.w;
    }

    // Cluster barrier: all CTAs' mbarrier init visible before any remote
    // arrive. Overlapped with the in-flight loads above.
    asm volatile("barrier.cluster.arrive.aligned;" ::: "memory");
    asm volatile("barrier.cluster.wait.aligned;" ::: "memory");

    float acc[36];
#pragma unroll
    for (int i = 0; i < 36; ++i) acc[i] = 0.0f;

#pragma unroll
    for (int k = 0; k < 4; ++k) {
        float sumsq_p = pv[0][k] * pv[0][k] + pv[1][k] * pv[1][k]
                      + pv[2][k] * pv[2][k] + pv[3][k] * pv[3][k];
        float sumsq_s = sv[0][k] * sv[0][k] + sv[1][k] * sv[1][k]
                      + sv[2][k] * sv[2][k] + sv[3][k] * sv[3][k];
        // x / max(||x||, 1e-12)  ==  x * rsqrt(max(||x||^2, 1e-24))
        float ip = rsqrtf(fmaxf(sumsq_p, 1e-24f));
        float is = rsqrtf(fmaxf(sumsq_s, 1e-24f));
        float v[8];
#pragma unroll
        for (int c = 0; c < 4; ++c) {
            v[c]     = pv[c][k] * ip;
            v[4 + c] = sv[c][k] * is;
        }
        int idx = 0;
#pragma unroll
        for (int i = 0; i < 8; ++i)
#pragma unroll
            for (int jj = i; jj < 8; ++jj)
                acc[idx++] += v[i] * v[jj];
    }

    // 3 butterfly rounds: lanes 0..3 hold sums of lanes {l, l+4, ..., l+28}.
#pragma unroll
    for (int off = 16; off >= 4; off >>= 1)
#pragma unroll
        for (int i = 0; i < 36; ++i)
            acc[i] += __shfl_down_sync(0xffffffffu, acc[i], off);

    if (lane < 4) {
        float* row = red[warp * 4 + lane];   // 16 warps x 4 = 64 rows
#pragma unroll
        for (int i = 0; i < 36; ++i) row[i] = acc[i];
    }
    __syncthreads();

    if (warp != 0) return;

    // ---- warp 0: column sums + DSMEM publish to rank 0 ----
    uint32_t rank;
    asm("mov.u32 %0, %%cluster_ctarank;" : "=r"(rank));

    {
        // Column 'lane': sum 64 rows, 8-way ILP + tree.
        float v[8];
#pragma unroll
        for (int j = 0; j < 8; ++j) v[j] = red[j][lane];
#pragma unroll
        for (int r = 8; r < 64; r += 8)
#pragma unroll
            for (int j = 0; j < 8; ++j) v[j] += red[r + j][lane];
        float s = ((v[0] + v[1]) + (v[2] + v[3]))
                + ((v[4] + v[5]) + (v[6] + v[7]));
        uint32_t raddr = mapa_rank0(smem_u32(&part[lane][rank]));
        asm volatile("st.shared::cluster.f32 [%0], %1;"
                     :: "r"(raddr), "f"(s) : "memory");

        if (lane < 4) {   // columns 32..35 on lanes 0..3
            float w[8];
#pragma unroll
            for (int j = 0; j < 8; ++j) w[j] = red[j][32 + lane];
#pragma unroll
            for (int r = 8; r < 64; r += 8)
#pragma unroll
                for (int j = 0; j < 8; ++j) w[j] += red[r + j][32 + lane];
            float s2 = ((w[0] + w[1]) + (w[2] + w[3]))
                     + ((w[4] + w[5]) + (w[6] + w[7]));
            uint32_t raddr2 = mapa_rank0(smem_u32(&part[32 + lane][rank]));
            asm volatile("st.shared::cluster.f32 [%0], %1;"
                         :: "r"(raddr2), "f"(s2) : "memory");
        }
    }
    __syncwarp();

    if (lane == 0) {
        // Release-arrive on rank 0's mbarrier (orders the DSMEM stores).
        uint32_t rmbar = mapa_rank0(mbar_addr);
        asm volatile("mbarrier.arrive.shared::cluster.b64 _, [%0];"
                     :: "r"(rmbar) : "memory");
    }
    if (rank != 0) return;

    // ---- rank 0, warp 0: wait for all 8 arrivals (acquire.cluster) ----
    asm volatile(
        "{\n\t"
        ".reg .pred P;\n\t"
        "W_%=:\n\t"
        "mbarrier.try_wait.parity.acquire.cluster.shared::cta.b64 P, [%0], 0;\n\t"
        "@!P bra W_%=;\n\t"
        "}"
        :: "r"(mbar_addr) : "memory");

    // lane l handles entry l; lanes 0..3 also entries 32..35.
    // Batch b's two CTA partials are columns {2b, 2b+1}.
    float val;
    {
        const float* r = part[lane];
        float m0 = r[0] + r[1], m1 = r[2] + r[3];
        float m2 = r[4] + r[5], m3 = r[6] + r[7];
        val = c_w[lane] * ((m0 * m0 + m1 * m1) + (m2 * m2 + m3 * m3));
    }
    if (lane < 4) {
        const float* r = part[32 + lane];
        float m0 = r[0] + r[1], m1 = r[2] + r[3];
        float m2 = r[4] + r[5], m3 = r[6] + r[7];
        val += c_w[32 + lane] * ((m0 * m0 + m1 * m1) + (m2 * m2 + m3 * m3));
    }

#pragma unroll
    for (int off = 16; off > 0; off >>= 1)
        val += __shfl_down_sync(0xffffffffu, val, off);

    if (lane == 0)
        out[0] = val * (1.0f / (4.0f * 4096.0f * 4096.0f));
}

extern "C" void kernel_launch(void* const* d_in, const int* in_sizes, int n_in,
                              void* d_out, int out_size)
{
    const float* xp = (const float*)d_in[0];  // x_pred [4,4,64,64] fp32
    const float* xs = (const float*)d_in[1];  // x_src  [4,4,64,64] fp32
    cosine_ssm_cluster_kernel<<<8, 512>>>(xp, xs, (float*)d_out);
}

// round 13
// speedup vs baseline: 1.0332x; 1.0037x over previous
#include <cuda_runtime.h>
#include <cstdint>

// Weight of packed upper-triangular entry e=(i,j), i<=j, of the 8x8 moment
// matrix M in loss_b = sum_e w_e * M_b[e]^2:
//   both in P-block (0..3): diag 1, off-diag 2   (||PP^T||_F^2)
//   i in P, j in S (4..7):  -2                   (-2||PS^T||_F^2)
//   both in S-block:        diag 1, off-diag 2   (||SS^T||_F^2)
__constant__ float c_w[36] = {
    1.f, 2.f, 2.f, 2.f, -2.f, -2.f, -2.f, -2.f,   // i=0
    1.f, 2.f, 2.f, -2.f, -2.f, -2.f, -2.f,        // i=1
    1.f, 2.f, -2.f, -2.f, -2.f, -2.f,             // i=2
    1.f, -2.f, -2.f, -2.f, -2.f,                  // i=3
    1.f, 2.f, 2.f, 2.f,                           // i=4
    1.f, 2.f, 2.f,                                // i=5
    1.f, 2.f,                                     // i=6
    1.f                                           // i=7
};

__device__ __forceinline__ uint32_t smem_u32(const void* p)
{
    uint32_t a;
    asm("{ .reg .u64 t; cvta.to.shared.u64 t, %1; cvt.u32.u64 %0, t; }"
        : "=r"(a) : "l"(p));
    return a;
}

// Map a local smem address to the same offset in cluster rank 0's smem.
__device__ __forceinline__ uint32_t mapa_rank0(uint32_t local_addr)
{
    uint32_t r;
    asm("mapa.shared::cluster.u32 %0, %1, 0;" : "=r"(r) : "r"(local_addr));
    return r;
}

// One cluster of 8 CTAs x 512 threads. CTA blk: batch b = blk>>1,
// half = blk&1 of the 4096 spatial positions. Each thread owns one float4
// group (4 positions). v_n = [p_n/||p_n||, s_n/||s_n||] in R^8; each CTA
// accumulates the 36 unique entries of sum_n v_n v_n^T for its slice and
// writes them into rank 0's smem via DSMEM, then arrives on rank 0's
// mbarrier. Rank 0 waits (8 arrivals) and evaluates
//   loss = sum_b (||PP^T||^2 - 2||PS^T||^2 + ||SS^T||^2) / (B*N*N)
// via the exact identity sum_nm (a_n.a_m)(b_n.b_m) = ||A B^T||_F^2.
// Split cluster barrier: arrive right after mbarrier init, wait only after
// all local compute — the barrier latency is hidden under real work.
__global__ void __launch_bounds__(512, 1) __cluster_dims__(8, 1, 1)
cosine_ssm_cluster_kernel(const float* __restrict__ xp,
                          const float* __restrict__ xs,
                          float* __restrict__ out)
{
    constexpr int N = 4096;
    __shared__ float red[64][37];   // stride 37 -> conflict-free columns
    __shared__ float part[36][9];   // [entry][rank], 9-pad -> conflict-free
    __shared__ __align__(8) unsigned long long mbar;

    const int blk  = blockIdx.x;
    const int b    = blk >> 1;      // batch (2 CTAs per batch)
    const int half = blk & 1;       // half of the spatial dim
    const int t    = threadIdx.x;
    const int warp = t >> 5;
    const int lane = t & 31;

    const uint32_t mbar_addr = smem_u32(&mbar);
    if (t == 0)
        asm volatile("mbarrier.init.shared.b64 [%0], 8;"
                     :: "r"(mbar_addr) : "memory");
    __syncthreads();   // init visible CTA-wide before this CTA's arrive

    // Split barrier, part 1: arrive now; wait much later (after compute).
    asm volatile("barrier.cluster.arrive.relaxed.aligned;" ::: "memory");

    const float* pb = xp + b * 4 * N;
    const float* sb = xs + b * 4 * N;
    const int g = half * 2048 + t * 4;   // starting spatial index

    float pv[4][4], sv[4][4];
#pragma unroll
    for (int c = 0; c < 4; ++c) {
        float4 a = *reinterpret_cast<const float4*>(pb + c * N + g);
        pv[c][0] = a.x; pv[c][1] = a.y; pv[c][2] = a.z; pv[c][3] = a.w;
        float4 q = *reinterpret_cast<const float4*>(sb + c * N + g);
        sv[c][0] = q.x; sv[c][1] = q.y; sv[c][2] = q.z; sv[c][3] = q.w;
    }

    float acc[36];
#pragma unroll
    for (int i = 0; i < 36; ++i) acc[i] = 0.0f;

#pragma unroll
    for (int k = 0; k < 4; ++k) {
        float sumsq_p = pv[0][k] * pv[0][k] + pv[1][k] * pv[1][k]
                      + pv[2][k] * pv[2][k] + pv[3][k] * pv[3][k];
        float sumsq_s = sv[0][k] * sv[0][k] + sv[1][k] * sv[1][k]
                      + sv[2][k] * sv[2][k] + sv[3][k] * sv[3][k];
        // x / max(||x||, 1e-12)  ==  x * rsqrt(max(||x||^2, 1e-24))
        float ip = rsqrtf(fmaxf(sumsq_p, 1e-24f));
        float is = rsqrtf(fmaxf(sumsq_s, 1e-24f));
        float v[8];
#pragma unroll
        for (int c = 0; c < 4; ++c) {
            v[c]     = pv[c][k] * ip;
            v[4 + c] = sv[c][k] * is;
        }
        int idx = 0;
#pragma unroll
        for (int i = 0; i < 8; ++i)
#pragma unroll
            for (int jj = i; jj < 8; ++jj)
                acc[idx++] += v[i] * v[jj];
    }

    // 3 butterfly rounds: lanes 0..3 hold sums of lanes {l, l+4, ..., l+28}.
#pragma unroll
    for (int off = 16; off >= 4; off >>= 1)
#pragma unroll
        for (int i = 0; i < 36; ++i)
            acc[i] += __shfl_down_sync(0xffffffffu, acc[i], off);

    if (lane < 4) {
        float* row = red[warp * 4 + lane];   // 16 warps x 4 = 64 rows
#pragma unroll
        for (int i = 0; i < 36; ++i) row[i] = acc[i];
    }
    __syncthreads();

    // Split barrier, part 2: by now every CTA arrived ~1000+ cycles ago,
    // so this completes on the fast path. Guarantees all CTAs' mbarrier
    // inits are visible before any remote arrive below. All 512 threads
    // still resident (aligned contract holds).
    asm volatile("barrier.cluster.wait.acquire.aligned;" ::: "memory");

    if (warp != 0) return;

    // ---- warp 0: column sums + DSMEM publish to rank 0 ----
    uint32_t rank;
    asm("mov.u32 %0, %%cluster_ctarank;" : "=r"(rank));

    {
        // Column 'lane': sum 64 rows, 8-way ILP + tree.
        float v[8];
#pragma unroll
        for (int j = 0; j < 8; ++j) v[j] = red[j][lane];
#pragma unroll
        for (int r = 8; r < 64; r += 8)
#pragma unroll
            for (int j = 0; j < 8; ++j) v[j] += red[r + j][lane];
        float s = ((v[0] + v[1]) + (v[2] + v[3]))
                + ((v[4] + v[5]) + (v[6] + v[7]));
        uint32_t raddr = mapa_rank0(smem_u32(&part[lane][rank]));
        asm volatile("st.shared::cluster.f32 [%0], %1;"
                     :: "r"(raddr), "f"(s) : "memory");

        if (lane < 4) {   // columns 32..35 on lanes 0..3
            float w[8];
#pragma unroll
            for (int j = 0; j < 8; ++j) w[j] = red[j][32 + lane];
#pragma unroll
            for (int r = 8; r < 64; r += 8)
#pragma unroll
                for (int j = 0; j < 8; ++j) w[j] += red[r + j][32 + lane];
            float s2 = ((w[0] + w[1]) + (w[2] + w[3]))
                     + ((w[4] + w[5]) + (w[6] + w[7]));
            uint32_t raddr2 = mapa_rank0(smem_u32(&part[32 + lane][rank]));
            asm volatile("st.shared::cluster.f32 [%0], %1;"
                         :: "r"(raddr2), "f"(s2) : "memory");
        }
    }
    __syncwarp();

    if (lane == 0) {
        // Release-arrive on rank 0's mbarrier (orders the DSMEM stores;
        // the __syncwarp chains the other lanes' stores into it).
        uint32_t rmbar = mapa_rank0(mbar_addr);
        asm volatile("mbarrier.arrive.shared::cluster.b64 _, [%0];"
                     :: "r"(rmbar) : "memory");
    }
    if (rank != 0) return;

    // ---- rank 0, warp 0: wait for all 8 arrivals (acquire.cluster) ----
    asm volatile(
        "{\n\t"
        ".reg .pred P;\n\t"
        "W_%=:\n\t"
        "mbarrier.try_wait.parity.acquire.cluster.shared::cta.b64 P, [%0], 0;\n\t"
        "@!P bra W_%=;\n\t"
        "}"
        :: "r"(mbar_addr) : "memory");

    // lane l handles entry l; lanes 0..3 also entries 32..35.
    // Batch b's two CTA partials are columns {2b, 2b+1}.
    float val;
    {
        const float* r = part[lane];
        float m0 = r[0] + r[1], m1 = r[2] + r[3];
        float m2 = r[4] + r[5], m3 = r[6] + r[7];
        val = c_w[lane] * ((m0 * m0 + m1 * m1) + (m2 * m2 + m3 * m3));
    }
    if (lane < 4) {
        const float* r = part[32 + lane];
        float m0 = r[0] + r[1], m1 = r[2] + r[3];
        float m2 = r[4] + r[5], m3 = r[6] + r[7];
        val += c_w[32 + lane] * ((m0 * m0 + m1 * m1) + (m2 * m2 + m3 * m3));
    }

#pragma unroll
    for (int off = 16; off > 0; off >>= 1)
        val += __shfl_down_sync(0xffffffffu, val, off);

    if (lane == 0)
        out[0] = val * (1.0f / (4.0f * 4096.0f * 4096.0f));
}

extern "C" void kernel_launch(void* const* d_in, const int* in_sizes, int n_in,
                              void* d_out, int out_size)
{
    const float* xp = (const float*)d_in[0];  // x_pred [4,4,64,64] fp32
    const float* xs = (const float*)d_in[1];  // x_src  [4,4,64,64] fp32
    cosine_ssm_cluster_kernel<<<8, 512>>>(xp, xs, (float*)d_out);
}